// round 5
// baseline (speedup 1.0000x reference)
#include <cuda_runtime.h>
#include <cstdint>

// BidPrefix: row = [rates[0..299], market_price, bid]
//   cp1[j] = prod_{k<j} rates[k]
//   out[0:B]  = cp1[bid]            (bid in [0,300])
//   out[B:2B] = cp1[mp] - cp1[mp+1] (mp  in [0,299])
//
// One warp per row. Loads are fully coalesced (lane t loads float2 #(t+32k)),
// staged through per-warp smem, read back per-lane-contiguous (10 floats/lane).
// Lane-local serial chain yields inner exclusive prefixes q_0..q_9; ONE warp
// shuffle product-scan yields cross-lane exclusive prefixes excl_t.
// cp1[x] = excl_{x/10} * q_{x/10}[x%10] answered via padded smem q-array.
// Early exit: skip float2 loads past maxelem = max(bid-1, mp).
//
// Bank analysis (8B banks, 16 per phase):
//   STS.64 write  f2 t+32k  -> bank t mod 16            : conflict-free
//   LDS.64 read   f2 5t+j   -> bank (5t+j) mod 16, gcd(5,16)=1 : conflict-free
//   q STS.32 stride 11 floats, gcd(11,32)=1             : conflict-free

static constexpr int SEQ = 300;
static constexpr int ROW = 302;
static constexpr int EPL = 10;        // elements per lane (lanes 0..29 real)
static constexpr int QSTRIDE = 11;
static constexpr int WARPS = 8;
static constexpr int DATA_F2 = 160;   // 5 * 32 float2 slots per warp

__global__ __launch_bounds__(256) void bidprefix_kernel(
    const float* __restrict__ in, float* __restrict__ out, int batch)
{
    __shared__ float2 dsm[WARPS][DATA_F2];        // 10.24 KB
    __shared__ float  qsm[WARPS][31 * QSTRIDE];   // 10.91 KB

    const int wib  = threadIdx.x >> 5;
    const int lane = threadIdx.x & 31;
    const int warp_id = blockIdx.x * WARPS + wib;
    if (warp_id >= batch) return;

    const float2* rowf2 = reinterpret_cast<const float2*>(in + (size_t)warp_id * ROW);

    // tail: floats [300]=mp, [301]=bid = float2 #150 (broadcast load, 1 wf)
    const float2 tail = rowf2[SEQ / 2];
    const int mp  = (int)tail.x;                 // 0..299
    const int bid = (int)tail.y;                 // 0..300
    const int maxelem = max(bid - 1, mp);        // highest rate index needed
    const int maxf2   = maxelem >> 1;            // <= 149, keeps loads in-bounds

    // coalesced load + smem stage; out-of-range slots get (1,1)
    #pragma unroll
    for (int k = 0; k < 5; k++) {
        const int i = lane + 32 * k;
        float2 v = make_float2(1.0f, 1.0f);
        if (i <= maxf2) v = rowf2[i];
        dsm[wib][i] = v;
    }
    __syncwarp();

    // per-lane contiguous read: floats 10t..10t+9 = float2 5t..5t+4
    const float2 a = dsm[wib][5 * lane + 0];
    const float2 b = dsm[wib][5 * lane + 1];
    const float2 c = dsm[wib][5 * lane + 2];
    const float2 d = dsm[wib][5 * lane + 3];
    const float2 e = dsm[wib][5 * lane + 4];

    // serial chain: intermediates = inner exclusive prefixes
    const float q1 = a.x;
    const float q2 = q1 * a.y;
    const float q3 = q2 * b.x;
    const float q4 = q3 * b.y;
    const float q5 = q4 * c.x;
    const float q6 = q5 * c.y;
    const float q7 = q6 * d.x;
    const float q8 = q7 * d.y;
    const float q9 = q8 * e.x;
    const float s  = q9 * e.y;                   // full local product

    if (lane <= 30) {
        float* p = &qsm[wib][lane * QSTRIDE];
        p[0] = 1.0f; p[1] = q1; p[2] = q2; p[3] = q3; p[4] = q4;
        p[5] = q5;   p[6] = q6; p[7] = q7; p[8] = q8; p[9] = q9;
    }

    // one inclusive warp scan (product) over lane products
    float incl = s;
    #pragma unroll
    for (int off = 1; off < 32; off <<= 1) {
        const float t = __shfl_up_sync(0xffffffffu, incl, off);
        if (lane >= off) incl *= t;
    }
    float excl = __shfl_up_sync(0xffffffffu, incl, 1);
    if (lane == 0) excl = 1.0f;

    __syncwarp();                                 // q STS -> LDS visibility

    // generic query: cp1[x] = excl_{x/10} * q_{x/10}[x%10]   (x in [0,300])
    const float* qbase = &qsm[wib][0];
    auto Q = [&](int x) -> float {
        const int dd = x / EPL;
        const int mm = x - dd * EPL;
        const float ee = __shfl_sync(0xffffffffu, excl, dd);
        return ee * qbase[dd * QSTRIDE + mm];     // uniform addr -> broadcast
    };

    const float surv = Q(bid);
    const float c0   = Q(mp);
    const float c1   = Q(mp + 1);

    if (lane == 0) {
        out[warp_id]         = surv;
        out[batch + warp_id] = c0 - c1;
    }
}

extern "C" void kernel_launch(void* const* d_in, const int* in_sizes, int n_in,
                              void* d_out, int out_size)
{
    const float* in  = (const float*)d_in[0];
    float*       out = (float*)d_out;
    const int batch  = in_sizes[0] / ROW;        // 500000

    const int threads = 32 * WARPS;              // 256
    const int blocks  = (batch + WARPS - 1) / WARPS;
    bidprefix_kernel<<<blocks, threads>>>(in, out, batch);
}

// round 6
// speedup vs baseline: 1.2838x; 1.2838x over previous
#include <cuda_runtime.h>
#include <cstdint>

// BidPrefix: row = [rates[0..299], market_price, bid]
//   cp1[j] = prod_{k<j} rates[k]
//   out[0:B]  = cp1[bid]            (bid in [0,300])
//   out[B:2B] = cp1[mp] - cp1[mp+1] (mp  in [0,299])
//
// One warp per row, INTERLEAVED ownership: lane t holds float2 chunks
// #(t+32k), k=0..4 -> all 5 loads perfectly coalesced, zero shared memory.
// Products are commutative, so cp1[x] = product over the SET {i < x}:
//   x = 64q + r  (q,r warp-uniform)
//   m_t = c_q[t] * (2t<r ? vx_q : 1) * (2t+1<r ? vy_q : 1)
//   cp1[x] = butterfly-product over lanes of m_t
// where c_j[t] = prod of lane-t chunk-pair products for rounds < j
// (free intermediates of a 5-deep chain). Skipped chunks (early exit past
// maxelem = max(bid-1,mp), and chunk #150 = tail) are (1,1) so all algebra
// holds unchanged.

static constexpr int ROW   = 302;
static constexpr int WARPS = 8;
static constexpr unsigned FULL = 0xffffffffu;

__global__ __launch_bounds__(256) void bidprefix_kernel(
    const float* __restrict__ in, float* __restrict__ out, int batch)
{
    const int wib  = threadIdx.x >> 5;
    const int lane = threadIdx.x & 31;
    const int warp_id = blockIdx.x * WARPS + wib;
    if (warp_id >= batch) return;

    const float2* rowf2 = reinterpret_cast<const float2*>(in + (size_t)warp_id * ROW);

    // tail: floats [300]=mp, [301]=bid = float2 #150 (1 line, broadcast)
    const float2 tail = rowf2[150];
    const int mp  = (int)tail.x;                  // 0..299
    const int bid = (int)tail.y;                  // 0..300
    const int maxf2 = max(bid - 1, mp) >> 1;      // last float2 chunk needed (0..149)

    // coalesced interleaved loads; out-of-range chunks = (1,1)
    float2 v0 = make_float2(1.f, 1.f), v1 = v0, v2 = v0, v3 = v0, v4 = v0;
    if (lane       <= maxf2) v0 = rowf2[lane];
    if (lane +  32 <= maxf2) v1 = rowf2[lane +  32];
    if (lane +  64 <= maxf2) v2 = rowf2[lane +  64];
    if (lane +  96 <= maxf2) v3 = rowf2[lane +  96];
    if (lane + 128 <= maxf2) v4 = rowf2[lane + 128];

    // vertical chain: c_j = prod over rounds < j of (vx*vy)   (c0 = 1)
    const float c1 = v0.x * v0.y;
    const float c2 = c1 * (v1.x * v1.y);
    const float c3 = c2 * (v2.x * v2.y);
    const float c4 = c3 * (v3.x * v3.y);
    // c5 never needed (x <= 300 -> q <= 4)

    const int lane2  = 2 * lane;

    // generic query: cp1[x], x in [0,300]
    auto Q = [&](int x) -> float {
        const int q = x >> 6;        // uniform
        const int r = x & 63;        // uniform
        // uniform selects over the chain / round values
        float cq = 1.0f;
        cq = (q == 1) ? c1 : cq;
        cq = (q == 2) ? c2 : cq;
        cq = (q == 3) ? c3 : cq;
        cq = (q == 4) ? c4 : cq;
        float vx = v0.x, vy = v0.y;
        vx = (q == 1) ? v1.x : vx;  vy = (q == 1) ? v1.y : vy;
        vx = (q == 2) ? v2.x : vx;  vy = (q == 2) ? v2.y : vy;
        vx = (q == 3) ? v3.x : vx;  vy = (q == 3) ? v3.y : vy;
        vx = (q == 4) ? v4.x : vx;  vy = (q == 4) ? v4.y : vy;

        float m = cq;
        m *= (lane2     < r) ? vx : 1.0f;
        m *= (lane2 + 1 < r) ? vy : 1.0f;

        #pragma unroll
        for (int off = 16; off; off >>= 1)
            m *= __shfl_xor_sync(FULL, m, off);
        return m;                    // product over all lanes, in every lane
    };

    const float surv = Q(bid);       // cp1[bid]
    const float pm   = Q(mp);        // cp1[mp]

    // rates[mp]: round qm = mp>>6, source lane = (mp&63)>>1, x/y by parity
    const int qm = mp >> 6;
    float rx = v0.x, ry = v0.y;
    rx = (qm == 1) ? v1.x : rx;  ry = (qm == 1) ? v1.y : ry;
    rx = (qm == 2) ? v2.x : rx;  ry = (qm == 2) ? v2.y : ry;
    rx = (qm == 3) ? v3.x : rx;  ry = (qm == 3) ? v3.y : ry;
    rx = (qm == 4) ? v4.x : rx;  ry = (qm == 4) ? v4.y : ry;
    const float rsel = (mp & 1) ? ry : rx;
    const float rmp  = __shfl_sync(FULL, rsel, (mp & 63) >> 1);

    if (lane == 0) {
        out[warp_id]         = surv;
        out[batch + warp_id] = pm - pm * rmp;   // cp1[mp] - cp1[mp+1]
    }
}

extern "C" void kernel_launch(void* const* d_in, const int* in_sizes, int n_in,
                              void* d_out, int out_size)
{
    const float* in  = (const float*)d_in[0];
    float*       out = (float*)d_out;
    const int batch  = in_sizes[0] / ROW;       // 500000

    const int threads = 32 * WARPS;             // 256
    const int blocks  = (batch + WARPS - 1) / WARPS;
    bidprefix_kernel<<<blocks, threads>>>(in, out, batch);
}

// round 7
// speedup vs baseline: 1.4549x; 1.1333x over previous
#include <cuda_runtime.h>
#include <cstdint>

// BidPrefix: row = [rates[0..299], market_price, bid]
//   cp1[j] = prod_{k<j} rates[k]
//   out[0:B]  = cp1[bid]            (bid in [0,300])
//   out[B:2B] = cp1[mp] - cp1[mp+1] (mp  in [0,299])
//
// One warp per row, interleaved ownership: lane t holds float2 chunks
// #(t+32k), k=0..4 (coalesced, no smem). cp1[x] is a product over the SET
// {i<x}; for x = 64q + r (warp-uniform):
//   m_t = c_q[t] * (2t<r ? vx_q : 1) * (2t+1<r ? vy_q : 1)
//   cp1[x] = butterfly-product over lanes
// Q(x) only ever touches indices < x, so chunks past maxelem may hold
// ANY value -> rounds 0..2 are loaded unconditionally, in parallel with the
// tail load (breaks the tail->load serialization; 41% of rows never wait on
// memory a second time). Rounds 3,4 stay predicated on maxf2 = max(bid-1,mp)/2
// (skip prob 41% / 73% -> bulk of the early-exit traffic saving).
// Round 4 lanes >= 22 are out of row bounds and never needed (idx >= 300).

static constexpr int ROW   = 302;
static constexpr int WARPS = 4;               // 128-thread blocks
static constexpr unsigned FULL = 0xffffffffu;

__global__ __launch_bounds__(128) void bidprefix_kernel(
    const float* __restrict__ in, float* __restrict__ out, int batch)
{
    const int wib  = threadIdx.x >> 5;
    const int lane = threadIdx.x & 31;
    const int warp_id = blockIdx.x * WARPS + wib;
    if (warp_id >= batch) return;

    const float2* rowf2 = reinterpret_cast<const float2*>(in + (size_t)warp_id * ROW);

    // issue tail + rounds 0..2 together (independent, MLP=4)
    const float2 tail = rowf2[150];           // floats [300]=mp, [301]=bid
    const float2 v0 = rowf2[lane];            // floats   0..63
    const float2 v1 = rowf2[lane + 32];       // floats  64..127
    const float2 v2 = rowf2[lane + 64];       // floats 128..191

    const int mp  = (int)tail.x;              // 0..299
    const int bid = (int)tail.y;              // 0..300
    const int maxf2 = max(bid - 1, mp) >> 1;  // last float2 chunk needed

    // rounds 3,4: predicated (traffic early-exit); skipped -> (1,1)
    float2 v3 = make_float2(1.f, 1.f), v4 = v3;
    if (lane +  96 <= maxf2) v3 = rowf2[lane +  96];   // floats 192..255
    if (lane + 128 <= maxf2) v4 = rowf2[lane + 128];   // floats 256..299 (lanes 0..21)

    // vertical chain: c_j = prod over rounds < j of (vx*vy)   (c0 = 1)
    const float c1 = v0.x * v0.y;
    const float c2 = c1 * (v1.x * v1.y);
    const float c3 = c2 * (v2.x * v2.y);
    const float c4 = c3 * (v3.x * v3.y);

    const int lane2 = 2 * lane;

    // ---- query bid ----
    const int qb = bid >> 6, rb = bid & 63;
    float cqb = 1.0f;
    cqb = (qb == 1) ? c1 : cqb;
    cqb = (qb == 2) ? c2 : cqb;
    cqb = (qb == 3) ? c3 : cqb;
    cqb = (qb == 4) ? c4 : cqb;
    float vxb = v0.x, vyb = v0.y;
    vxb = (qb == 1) ? v1.x : vxb;  vyb = (qb == 1) ? v1.y : vyb;
    vxb = (qb == 2) ? v2.x : vxb;  vyb = (qb == 2) ? v2.y : vyb;
    vxb = (qb == 3) ? v3.x : vxb;  vyb = (qb == 3) ? v3.y : vyb;
    vxb = (qb == 4) ? v4.x : vxb;  vyb = (qb == 4) ? v4.y : vyb;
    float m1 = cqb;
    m1 *= (lane2     < rb) ? vxb : 1.0f;
    m1 *= (lane2 + 1 < rb) ? vyb : 1.0f;

    // ---- query mp ----
    const int qm = mp >> 6, rm = mp & 63;
    float cqm = 1.0f;
    cqm = (qm == 1) ? c1 : cqm;
    cqm = (qm == 2) ? c2 : cqm;
    cqm = (qm == 3) ? c3 : cqm;
    cqm = (qm == 4) ? c4 : cqm;
    float vxm = v0.x, vym = v0.y;
    vxm = (qm == 1) ? v1.x : vxm;  vym = (qm == 1) ? v1.y : vym;
    vxm = (qm == 2) ? v2.x : vxm;  vym = (qm == 2) ? v2.y : vym;
    vxm = (qm == 3) ? v3.x : vxm;  vym = (qm == 3) ? v3.y : vym;
    vxm = (qm == 4) ? v4.x : vxm;  vym = (qm == 4) ? v4.y : vym;
    float m2 = cqm;
    m2 *= (lane2     < rm) ? vxm : 1.0f;
    m2 *= (lane2 + 1 < rm) ? vym : 1.0f;

    // combined butterfly: two independent chains pipeline the SHFL latency
    #pragma unroll
    for (int off = 16; off; off >>= 1) {
        const float t1 = __shfl_xor_sync(FULL, m1, off);
        const float t2 = __shfl_xor_sync(FULL, m2, off);
        m1 *= t1;
        m2 *= t2;
    }
    // m1 = cp1[bid], m2 = cp1[mp] in every lane

    // rates[mp]: reuse mp's selected round values (owner lane rm>>1, parity rm&1)
    const float rsel = (mp & 1) ? vym : vxm;
    const float rmp  = __shfl_sync(FULL, rsel, rm >> 1);

    if (lane == 0) {
        out[warp_id]         = m1;
        out[batch + warp_id] = m2 - m2 * rmp;   // cp1[mp] - cp1[mp+1]
    }
}

extern "C" void kernel_launch(void* const* d_in, const int* in_sizes, int n_in,
                              void* d_out, int out_size)
{
    const float* in  = (const float*)d_in[0];
    float*       out = (float*)d_out;
    const int batch  = in_sizes[0] / ROW;       // 500000

    const int threads = 32 * WARPS;             // 128
    const int blocks  = (batch + WARPS - 1) / WARPS;
    bidprefix_kernel<<<blocks, threads>>>(in, out, batch);
}